// round 4
// baseline (speedup 1.0000x reference)
#include <cuda_runtime.h>
#include <cuda_bf16.h>
#include <cstdint>

#define T     4096
#define EMB   256
#define H2    256
#define G     1024
#define TAGS  6
#define NEG   (-10000.0f)

__device__ float g_zin[2][T][G];
__device__ float g_hs[T][2 * H2];
__device__ float g_feats[T][TAGS];

__device__ __forceinline__ unsigned smem_u32(const void* p) {
    return (unsigned)__cvta_generic_to_shared(p);
}
__device__ __forceinline__ unsigned mapa_sh(unsigned a, unsigned r) {
    unsigned d;
    asm("mapa.shared::cluster.u32 %0, %1, %2;" : "=r"(d) : "r"(a), "r"(r));
    return d;
}
__device__ __forceinline__ unsigned long long fma2(unsigned long long a,
                                                   unsigned long long b,
                                                   unsigned long long c) {
    unsigned long long d;
    asm("fma.rn.f32x2 %0, %1, %2, %3;" : "=l"(d) : "l"(a), "l"(b), "l"(c));
    return d;
}
__device__ __forceinline__ float2 u2f(unsigned long long v) {
    float2 r;
    asm("mov.b64 {%0, %1}, %2;" : "=f"(r.x), "=f"(r.y) : "l"(v));
    return r;
}
__device__ __forceinline__ void mbar_init(unsigned a, unsigned c) {
    asm volatile("mbarrier.init.shared.b64 [%0], %1;" :: "r"(a), "r"(c) : "memory");
}
__device__ __forceinline__ void mbar_wait(unsigned a, unsigned p) {
    asm volatile(
        "{\n\t.reg .pred P;\n"
        "W%=:\n\t"
        "mbarrier.try_wait.parity.acquire.cluster.shared::cta.b64 P, [%0], %1, 0x989680;\n\t"
        "@P bra D%=;\n\t"
        "bra W%=;\n"
        "D%=:\n\t}" :: "r"(a), "r"(p) : "memory");
}
__device__ __forceinline__ void mbar_arrive_rel(unsigned a) {
    asm volatile("mbarrier.arrive.release.cluster.shared::cluster.b64 _, [%0];"
                 :: "r"(a) : "memory");
}
__device__ __forceinline__ void st_cl_v4(unsigned a, float4 v) {
    asm volatile("st.shared::cluster.v4.f32 [%0], {%1,%2,%3,%4};"
                 :: "r"(a), "f"(v.x), "f"(v.y), "f"(v.z), "f"(v.w) : "memory");
}
__device__ __forceinline__ void cl_sync() {
    asm volatile("barrier.cluster.arrive.aligned;\n\tbarrier.cluster.wait.aligned;" ::: "memory");
}
__device__ __forceinline__ float sigf(float x) { return 1.0f / (1.0f + __expf(-x)); }
__device__ __forceinline__ float tanh_(float x) { return 2.0f * sigf(2.0f * x) - 1.0f; }

// ---- Kernel 1: z_in = emb[sentence] @ W_ih^T + b_ih + b_hh (both dirs) ----
__global__ void __launch_bounds__(256)
k_zin(const int* __restrict__ sent, const float* __restrict__ emb,
      const float* __restrict__ wihf, const float* __restrict__ wihb,
      const float* __restrict__ bihf, const float* __restrict__ bhhf,
      const float* __restrict__ bihb, const float* __restrict__ bhhb) {
    __shared__ float As[64][68];
    __shared__ float Bs[64][68];
    __shared__ int ss[64];
    int tid = threadIdx.x;
    int n0 = blockIdx.x * 64, t0 = blockIdx.y * 64;
    if (tid < 64) ss[tid] = sent[t0 + tid];
    __syncthreads();
    int tm = (tid >> 4) << 2, tn = (tid & 15) << 2;
    float acc[4][4] = {};
    for (int k0 = 0; k0 < 256; k0 += 64) {
        #pragma unroll
        for (int l = 0; l < 4; l++) {
            int idx = tid + l * 256, r = idx >> 4, c = idx & 15;
            *(float4*)&As[r][c * 4] =
                *(const float4*)&emb[(size_t)ss[r] * EMB + k0 + c * 4];
            int n = n0 + r;
            const float* w = (n < 1024) ? wihf : wihb;
            *(float4*)&Bs[r][c * 4] =
                *(const float4*)&w[(size_t)(n & 1023) * EMB + k0 + c * 4];
        }
        __syncthreads();
        #pragma unroll
        for (int kk = 0; kk < 16; kk++) {
            float4 a[4], b[4];
            #pragma unroll
            for (int i = 0; i < 4; i++) a[i] = *(const float4*)&As[tm + i][kk * 4];
            #pragma unroll
            for (int j = 0; j < 4; j++) b[j] = *(const float4*)&Bs[tn + j][kk * 4];
            #pragma unroll
            for (int i = 0; i < 4; i++)
                #pragma unroll
                for (int j = 0; j < 4; j++)
                    acc[i][j] += a[i].x * b[j].x + a[i].y * b[j].y +
                                 a[i].z * b[j].z + a[i].w * b[j].w;
        }
        __syncthreads();
    }
    int nb = n0 + tn, d = nb >> 10, nn = nb & 1023;
    const float* bi = d ? bihb : bihf;
    const float* bh = d ? bhhb : bhhf;
    float4 bias = { bi[nn] + bh[nn], bi[nn + 1] + bh[nn + 1],
                    bi[nn + 2] + bh[nn + 2], bi[nn + 3] + bh[nn + 3] };
    #pragma unroll
    for (int i = 0; i < 4; i++) {
        float4 v = { acc[i][0] + bias.x, acc[i][1] + bias.y,
                     acc[i][2] + bias.z, acc[i][3] + bias.w };
        *(float4*)&g_zin[d][t0 + tm + i][nn] = v;
    }
}

// ---- Kernel 2: BiLSTM recurrence. One 8-CTA cluster per direction. --------
__global__ void __launch_bounds__(256, 1) __cluster_dims__(8, 1, 1)
k_lstm(const float* __restrict__ whhf, const float* __restrict__ whhb,
       const float* __restrict__ h0, const float* __restrict__ c0) {
    __shared__ __align__(16) float h_buf[2][H2];
    __shared__ float zbuf[128];
    __shared__ __align__(16) float hstage[32];
    __shared__ __align__(8) unsigned long long mbar[2];

    int tid = threadIdx.x;
    int dir = blockIdx.x >> 3, rank = blockIdx.x & 7;
    int row = tid >> 1, half = tid & 1;
    int gate = row >> 5, unit = row & 31;
    int grow = gate * H2 + rank * 32 + unit;
    const float* whh = dir ? whhb : whhf;

    unsigned long long w[64];
    {
        const ulonglong2* ws = (const ulonglong2*)(whh + (size_t)grow * H2 + half * 128);
        #pragma unroll
        for (int k = 0; k < 32; k++) {
            ulonglong2 v = ws[k];
            w[2 * k] = v.x; w[2 * k + 1] = v.y;
        }
    }
    if (tid == 0) { mbar_init(smem_u32(&mbar[0]), 8); mbar_init(smem_u32(&mbar[1]), 8); }
    h_buf[0][tid] = h0[dir * H2 + tid];
    float c_state = (tid < 32) ? c0[dir * H2 + rank * 32 + tid] : 0.0f;
    cl_sync();

    unsigned bar0 = smem_u32(&mbar[0]), bar1 = smem_u32(&mbar[1]);
    int ph0 = 0, ph1 = 0;
    const float* zin = &g_zin[dir][0][0];
    float zpre = 0.0f;
    if (half == 0) zpre = __ldg(&zin[(size_t)(dir ? T - 1 : 0) * G + grow]);

    for (int s = 0; s < T; s++) {
        int t = dir ? (T - 1 - s) : s;
        int buf = s & 1;
        if (s > 0) {
            if (buf) { mbar_wait(bar1, ph1); ph1 ^= 1; }
            else     { mbar_wait(bar0, ph0); ph0 ^= 1; }
        }
        const ulonglong2* hb2 = (const ulonglong2*)&h_buf[buf][half * 128];
        unsigned long long a0 = 0, a1 = 0, a2 = 0, a3 = 0;
        #pragma unroll
        for (int k = 0; k < 16; k++) {
            ulonglong2 hA = hb2[2 * k], hB = hb2[2 * k + 1];
            a0 = fma2(w[4 * k + 0], hA.x, a0);
            a1 = fma2(w[4 * k + 1], hA.y, a1);
            a2 = fma2(w[4 * k + 2], hB.x, a2);
            a3 = fma2(w[4 * k + 3], hB.y, a3);
        }
        float2 f0 = u2f(a0), f1 = u2f(a1), f2 = u2f(a2), f3 = u2f(a3);
        float sum = ((f0.x + f0.y) + (f1.x + f1.y)) + ((f2.x + f2.y) + (f3.x + f3.y));
        sum += __shfl_xor_sync(0xFFFFFFFFu, sum, 1);
        if (half == 0) zbuf[row] = sum + zpre;
        if (half == 0 && s + 1 < T)
            zpre = __ldg(&zin[(size_t)(dir ? T - 2 - s : s + 1) * G + grow]);
        __syncthreads();

        if (tid < 32) {
            float zi = zbuf[tid], zf = zbuf[32 + tid], zg = zbuf[64 + tid], zo = zbuf[96 + tid];
            float ig = sigf(zi), fg = sigf(zf), gg = tanh_(zg), og = sigf(zo);
            c_state = fg * c_state + ig * gg;
            float h = og * tanh_(c_state);
            g_hs[t][dir * H2 + rank * 32 + tid] = h;
            hstage[tid] = h;
            __syncwarp();
            if (s + 1 < T && tid < 8) {
                int nb = buf ^ 1;
                unsigned la = smem_u32(&h_buf[nb][rank * 32]);
                unsigned ra = mapa_sh(la, (unsigned)tid);
                const float4* src = (const float4*)hstage;
                #pragma unroll
                for (int j = 0; j < 8; j++) st_cl_v4(ra + 16 * j, src[j]);
                mbar_arrive_rel(mapa_sh(nb ? bar1 : bar0, (unsigned)tid));
            }
        }
        __syncthreads();   // order zbuf/hstage reads before next-step writes
    }
    cl_sync();             // no CTA exits while peers may still touch DSMEM
}

// ---- Kernel 3: feats = [hf|hb] @ W_out^T + b_out ---------------------------
__global__ void __launch_bounds__(384)
k_feats(const float* __restrict__ Wout, const float* __restrict__ bout) {
    __shared__ float Ws[TAGS * 512];
    __shared__ float bs[TAGS];
    int tid = threadIdx.x;
    for (int i = tid; i < TAGS * 512; i += 384) Ws[i] = Wout[i];
    if (tid < TAGS) bs[tid] = bout[tid];
    __syncthreads();
    int t = blockIdx.x * 64 + tid / TAGS;
    int tag = tid % TAGS;
    const float* h = g_hs[t];
    float acc = 0.0f;
    #pragma unroll 8
    for (int k = 0; k < 512; k += 4) {
        float4 hv = *(const float4*)&h[k];
        float4 wv = *(const float4*)&Ws[tag * 512 + k];
        acc += hv.x * wv.x + hv.y * wv.y + hv.z * wv.z + hv.w * wv.w;
    }
    g_feats[t][tag] = acc + bs[tag];
}

// ---- Kernel 4: Viterbi forward + backtrace (single warp) -------------------
__global__ void __launch_bounds__(32)
k_vit(const float* __restrict__ trans, float* __restrict__ out, int out_size) {
    __shared__ unsigned bpw[T];
    float tr[TAGS][TAGS];
    #pragma unroll
    for (int a = 0; a < TAGS; a++)
        #pragma unroll
        for (int b = 0; b < TAGS; b++) tr[a][b] = __ldg(&trans[a * TAGS + b]);

    float fv[TAGS];
    #pragma unroll
    for (int i = 0; i < TAGS; i++) fv[i] = NEG;
    fv[3] = 0.0f;  // START

    const float* fp = &g_feats[0][0];
    float ft[TAGS];
    #pragma unroll
    for (int i = 0; i < TAGS; i++) ft[i] = __ldg(&fp[i]);

    for (int t = 0; t < T; t++) {
        float fn[TAGS];
        int tn = (t + 1 < T) ? (t + 1) : t;
        #pragma unroll
        for (int i = 0; i < TAGS; i++) fn[i] = __ldg(&fp[tn * TAGS + i]);
        float nfv[TAGS];
        unsigned wrd = 0;
        #pragma unroll
        for (int to = 0; to < TAGS; to++) {
            float best = tr[to][0] + fv[0];
            int bp = 0;
            #pragma unroll
            for (int f = 1; f < TAGS; f++) {
                float c = tr[to][f] + fv[f];
                if (c > best) { best = c; bp = f; }   // first-max (jnp.argmax)
            }
            nfv[to] = best + ft[to];
            wrd |= (unsigned)bp << (4 * to);
        }
        #pragma unroll
        for (int i = 0; i < TAGS; i++) { fv[i] = nfv[i]; ft[i] = fn[i]; }
        if (threadIdx.x == 0) bpw[t] = wrd;
    }

    float best = fv[0] + tr[4][0];   // STOP row
    int bt = 0;
    #pragma unroll
    for (int f = 1; f < TAGS; f++) {
        float c = fv[f] + tr[4][f];
        if (c > best) { best = c; bt = f; }
    }

    if (threadIdx.x == 0) {
        int off = 0;
        if (out_size == 1) { out[0] = best; return; }
        if (out_size >= T + 1) { out[0] = best; off = 1; }
        int tag = bt;
        for (int t = T - 1; t >= 0; t--) {
            out[off + t] = (float)tag;
            tag = (int)((bpw[t] >> (4 * tag)) & 15u);
        }
    }
}

extern "C" void kernel_launch(void* const* d_in, const int* in_sizes, int n_in,
                              void* d_out, int out_size) {
    const int*   sent  = (const int*)  d_in[0];
    const float* emb   = (const float*)d_in[1];
    const float* wihf  = (const float*)d_in[2];
    const float* whhf  = (const float*)d_in[3];
    const float* bihf  = (const float*)d_in[4];
    const float* bhhf  = (const float*)d_in[5];
    const float* wihb  = (const float*)d_in[6];
    const float* whhb  = (const float*)d_in[7];
    const float* bihb  = (const float*)d_in[8];
    const float* bhhb  = (const float*)d_in[9];
    const float* Wout  = (const float*)d_in[10];
    const float* bout  = (const float*)d_in[11];
    const float* trans = (const float*)d_in[12];
    const float* h0    = (const float*)d_in[13];
    const float* c0    = (const float*)d_in[14];

    dim3 gz(2048 / 64, T / 64);
    k_zin<<<gz, 256>>>(sent, emb, wihf, wihb, bihf, bhhf, bihb, bhhb);
    k_lstm<<<16, 256>>>(whhf, whhb, h0, c0);
    k_feats<<<T / 64, 384>>>(Wout, bout);
    k_vit<<<1, 32>>>(trans, (float*)d_out, out_size);
}

// round 6
// speedup vs baseline: 1.2468x; 1.2468x over previous
#include <cuda_runtime.h>
#include <cuda_bf16.h>
#include <cstdint>

#define T     4096
#define EMB   256
#define H2    256
#define G     1024
#define TAGS  6
#define NEG   (-10000.0f)
#define CPD   16   // CTAs per direction (cluster size)

__device__ float g_zin[2][T][G];
__device__ float g_hs[T][2 * H2];
__device__ __align__(16) float g_feats[T][TAGS];

__device__ __forceinline__ unsigned smem_u32(const void* p) {
    return (unsigned)__cvta_generic_to_shared(p);
}
__device__ __forceinline__ unsigned mapa_sh(unsigned a, unsigned r) {
    unsigned d;
    asm("mapa.shared::cluster.u32 %0, %1, %2;" : "=r"(d) : "r"(a), "r"(r));
    return d;
}
__device__ __forceinline__ unsigned long long fma2(unsigned long long a,
                                                   unsigned long long b,
                                                   unsigned long long c) {
    unsigned long long d;
    asm("fma.rn.f32x2 %0, %1, %2, %3;" : "=l"(d) : "l"(a), "l"(b), "l"(c));
    return d;
}
__device__ __forceinline__ float2 u2f(unsigned long long v) {
    float2 r;
    asm("mov.b64 {%0, %1}, %2;" : "=f"(r.x), "=f"(r.y) : "l"(v));
    return r;
}
__device__ __forceinline__ void mbar_init(unsigned a, unsigned c) {
    asm volatile("mbarrier.init.shared.b64 [%0], %1;" :: "r"(a), "r"(c) : "memory");
}
__device__ __forceinline__ void mbar_wait(unsigned a, unsigned p) {
    asm volatile(
        "{\n\t.reg .pred P;\n"
        "W%=:\n\t"
        "mbarrier.try_wait.parity.acquire.cluster.shared::cta.b64 P, [%0], %1, 0x989680;\n\t"
        "@P bra D%=;\n\t"
        "bra W%=;\n"
        "D%=:\n\t}" :: "r"(a), "r"(p) : "memory");
}
__device__ __forceinline__ void mbar_arrive_rel(unsigned a) {
    asm volatile("mbarrier.arrive.release.cluster.shared::cluster.b64 _, [%0];"
                 :: "r"(a) : "memory");
}
__device__ __forceinline__ void st_cl_v4(unsigned a, float4 v) {
    asm volatile("st.shared::cluster.v4.f32 [%0], {%1,%2,%3,%4};"
                 :: "r"(a), "f"(v.x), "f"(v.y), "f"(v.z), "f"(v.w) : "memory");
}
__device__ __forceinline__ void cl_sync() {
    asm volatile("barrier.cluster.arrive.aligned;\n\tbarrier.cluster.wait.aligned;" ::: "memory");
}
__device__ __forceinline__ void bar_sync1() {
    asm volatile("bar.sync 1, 128;" ::: "memory");
}
__device__ __forceinline__ void bar_arrive1() {
    asm volatile("bar.arrive 1, 128;" ::: "memory");
}
__device__ __forceinline__ float sigf(float x) { return 1.0f / (1.0f + __expf(-x)); }
__device__ __forceinline__ float tanh_(float x) { return 2.0f * sigf(2.0f * x) - 1.0f; }

// ---- Kernel 1: z_in = emb[sentence] @ W_ih^T + b_ih + b_hh (both dirs) ----
__global__ void __launch_bounds__(256)
k_zin(const int* __restrict__ sent, const float* __restrict__ emb,
      const float* __restrict__ wihf, const float* __restrict__ wihb,
      const float* __restrict__ bihf, const float* __restrict__ bhhf,
      const float* __restrict__ bihb, const float* __restrict__ bhhb) {
    __shared__ float As[64][68];
    __shared__ float Bs[64][68];
    __shared__ int ss[64];
    int tid = threadIdx.x;
    int n0 = blockIdx.x * 64, t0 = blockIdx.y * 64;
    if (tid < 64) ss[tid] = sent[t0 + tid];
    __syncthreads();
    int tm = (tid >> 4) << 2, tn = (tid & 15) << 2;
    float acc[4][4] = {};
    for (int k0 = 0; k0 < 256; k0 += 64) {
        #pragma unroll
        for (int l = 0; l < 4; l++) {
            int idx = tid + l * 256, r = idx >> 4, c = idx & 15;
            *(float4*)&As[r][c * 4] =
                *(const float4*)&emb[(size_t)ss[r] * EMB + k0 + c * 4];
            int n = n0 + r;
            const float* w = (n < 1024) ? wihf : wihb;
            *(float4*)&Bs[r][c * 4] =
                *(const float4*)&w[(size_t)(n & 1023) * EMB + k0 + c * 4];
        }
        __syncthreads();
        #pragma unroll
        for (int kk = 0; kk < 16; kk++) {
            float4 a[4], b[4];
            #pragma unroll
            for (int i = 0; i < 4; i++) a[i] = *(const float4*)&As[tm + i][kk * 4];
            #pragma unroll
            for (int j = 0; j < 4; j++) b[j] = *(const float4*)&Bs[tn + j][kk * 4];
            #pragma unroll
            for (int i = 0; i < 4; i++)
                #pragma unroll
                for (int j = 0; j < 4; j++)
                    acc[i][j] += a[i].x * b[j].x + a[i].y * b[j].y +
                                 a[i].z * b[j].z + a[i].w * b[j].w;
        }
        __syncthreads();
    }
    int nb = n0 + tn, d = nb >> 10, nn = nb & 1023;
    const float* bi = d ? bihb : bihf;
    const float* bh = d ? bhhb : bhhf;
    float4 bias = { bi[nn] + bh[nn], bi[nn + 1] + bh[nn + 1],
                    bi[nn + 2] + bh[nn + 2], bi[nn + 3] + bh[nn + 3] };
    #pragma unroll
    for (int i = 0; i < 4; i++) {
        float4 v = { acc[i][0] + bias.x, acc[i][1] + bias.y,
                     acc[i][2] + bias.z, acc[i][3] + bias.w };
        *(float4*)&g_zin[d][t0 + tm + i][nn] = v;
    }
}

// ---- Kernel 2: BiLSTM. 16-CTA cluster per direction; R3-exact row math. ---
// Thread (row, half): row 0..63 local, half 0/1; sums 128 contiguous cols
// with interleaved a0..a3 accumulators + pair shuffle — identical FP order
// to the proven R3 kernel. Activations applied pre-barrier by the half==0
// owner thread (same expression, same input -> same bits).
__global__ void __launch_bounds__(128, 1)
k_lstm(const float* __restrict__ whhf, const float* __restrict__ whhb,
       const float* __restrict__ h0, const float* __restrict__ c0) {
    __shared__ __align__(16) float h_buf[2][H2];
    __shared__ float zbuf[64];
    __shared__ __align__(16) float hstage[16];
    __shared__ __align__(8) unsigned long long mbar[2];

    int tid = threadIdx.x;
    unsigned crank;
    asm("mov.u32 %0, %%cluster_ctarank;" : "=r"(crank));
    int dir = (int)(blockIdx.x >> 4);
    int rank = (int)(crank);
    int row = tid >> 1, half = tid & 1;
    int gate = row >> 4, unit = row & 15;
    int grow = gate * H2 + rank * 16 + unit;
    const float* whh = dir ? whhb : whhf;

    // 128 weights (64 packed f32x2) per thread, register-resident (R3 layout)
    unsigned long long w[64];
    {
        const ulonglong2* ws = (const ulonglong2*)(whh + (size_t)grow * H2 + half * 128);
        #pragma unroll
        for (int k = 0; k < 32; k++) {
            ulonglong2 v = ws[k];
            w[2 * k] = v.x; w[2 * k + 1] = v.y;
        }
    }
    if (tid == 0) { mbar_init(smem_u32(&mbar[0]), CPD); mbar_init(smem_u32(&mbar[1]), CPD); }
    h_buf[0][tid] = h0[dir * H2 + tid];
    h_buf[0][tid + 128] = h0[dir * H2 + tid + 128];
    float c_state = (tid < 16) ? c0[dir * H2 + rank * 16 + tid] : 0.0f;
    cl_sync();

    unsigned bar0 = smem_u32(&mbar[0]), bar1 = smem_u32(&mbar[1]);
    int ph0 = 0, ph1 = 0;
    const float* zin = &g_zin[dir][0][0];
    float zpre = 0.0f;
    if (half == 0) zpre = __ldg(&zin[(size_t)(dir ? T - 1 : 0) * G + grow]);

    for (int s = 0; s < T; s++) {
        int t = dir ? (T - 1 - s) : s;
        int buf = s & 1;
        if (s > 0) {
            if (buf) { mbar_wait(bar1, ph1); ph1 ^= 1; }
            else     { mbar_wait(bar0, ph0); ph0 ^= 1; }
        }
        // R3-exact 128-column partial dot, packed f32x2
        const ulonglong2* hb2 = (const ulonglong2*)&h_buf[buf][half * 128];
        unsigned long long a0 = 0, a1 = 0, a2 = 0, a3 = 0;
        #pragma unroll
        for (int k = 0; k < 16; k++) {
            ulonglong2 hA = hb2[2 * k], hB = hb2[2 * k + 1];
            a0 = fma2(w[4 * k + 0], hA.x, a0);
            a1 = fma2(w[4 * k + 1], hA.y, a1);
            a2 = fma2(w[4 * k + 2], hB.x, a2);
            a3 = fma2(w[4 * k + 3], hB.y, a3);
        }
        float2 f0 = u2f(a0), f1 = u2f(a1), f2 = u2f(a2), f3 = u2f(a3);
        float sum = ((f0.x + f0.y) + (f1.x + f1.y)) + ((f2.x + f2.y) + (f3.x + f3.y));
        sum += __shfl_xor_sync(0xFFFFFFFFu, sum, 1);
        if (half == 0) {
            float z = sum + zpre;
            // pre-apply activation (gate 2 = g uses tanh; i/f/o sigmoid)
            zbuf[row] = (gate == 2) ? tanh_(z) : sigf(z);
            if (s + 1 < T)
                zpre = __ldg(&zin[(size_t)(dir ? T - 2 - s : s + 1) * G + grow]);
        }

        if (tid < 32) {
            bar_sync1();   // wait for all 64 zbuf writes (all 128 threads arrive)
            if (tid < 16) {
                float ig = zbuf[tid], fg = zbuf[16 + tid],
                      gg = zbuf[32 + tid], og = zbuf[48 + tid];
                c_state = fg * c_state + ig * gg;
                float h = og * tanh_(c_state);
                hstage[tid] = h;
            }
            __syncwarp();
            if (tid < CPD && s + 1 < T) {
                int nb = buf ^ 1;
                unsigned la = smem_u32(&h_buf[nb][rank * 16]);
                unsigned ra = mapa_sh(la, (unsigned)tid);
                const float4* src = (const float4*)hstage;
                #pragma unroll
                for (int q = 0; q < 4; q++) st_cl_v4(ra + 16 * q, src[q]);
                mbar_arrive_rel(mapa_sh(nb ? bar1 : bar0, (unsigned)tid));
            }
            if (tid < 16)
                g_hs[t][dir * H2 + rank * 16 + tid] = hstage[tid];
        } else {
            bar_arrive1(); // non-blocking; WAR safety via the mbar arrive chain
        }
    }
    cl_sync();
}

// ---- Kernel 3: feats = [hf|hb] @ W_out^T + b_out ---------------------------
__global__ void __launch_bounds__(384)
k_feats(const float* __restrict__ Wout, const float* __restrict__ bout) {
    __shared__ float Ws[TAGS * 512];
    __shared__ float bs[TAGS];
    int tid = threadIdx.x;
    for (int i = tid; i < TAGS * 512; i += 384) Ws[i] = Wout[i];
    if (tid < TAGS) bs[tid] = bout[tid];
    __syncthreads();
    int t = blockIdx.x * 64 + tid / TAGS;
    int tag = tid % TAGS;
    const float* h = g_hs[t];
    float acc = 0.0f;
    #pragma unroll 8
    for (int k = 0; k < 512; k += 4) {
        float4 hv = *(const float4*)&h[k];
        float4 wv = *(const float4*)&Ws[tag * 512 + k];
        acc += hv.x * wv.x + hv.y * wv.y + hv.z * wv.z + hv.w * wv.w;
    }
    g_feats[t][tag] = acc + bs[tag];
}

// ---- Kernel 4: Viterbi, feats+backptrs staged in smem (exact FP order) -----
extern __shared__ char vsm[];
__global__ void __launch_bounds__(256)
k_vit(const float* __restrict__ trans, float* __restrict__ out, int out_size) {
    float*    fs  = (float*)vsm;                       // T*TAGS floats
    unsigned* bpw = (unsigned*)(vsm + T * TAGS * 4);   // T words
    int tid = threadIdx.x;

    const float4* src = (const float4*)&g_feats[0][0];
    float4* dst = (float4*)fs;
    for (int i = tid; i < T * TAGS / 4; i += 256) dst[i] = src[i];
    __syncthreads();
    if (tid >= 32) return;

    float tr[TAGS][TAGS];
    #pragma unroll
    for (int a = 0; a < TAGS; a++)
        #pragma unroll
        for (int b = 0; b < TAGS; b++) tr[a][b] = __ldg(&trans[a * TAGS + b]);

    float fv[TAGS];
    #pragma unroll
    for (int i = 0; i < TAGS; i++) fv[i] = NEG;
    fv[3] = 0.0f;  // START

    float ft[TAGS];
    #pragma unroll
    for (int i = 0; i < TAGS; i++) ft[i] = fs[i];

    for (int t = 0; t < T; t++) {
        float fn[TAGS];
        int tn = (t + 1 < T) ? (t + 1) : t;
        #pragma unroll
        for (int i = 0; i < TAGS; i++) fn[i] = fs[tn * TAGS + i];
        float nfv[TAGS];
        unsigned wrd = 0;
        #pragma unroll
        for (int to = 0; to < TAGS; to++) {
            float best = tr[to][0] + fv[0];
            int bp = 0;
            #pragma unroll
            for (int f = 1; f < TAGS; f++) {
                float c = tr[to][f] + fv[f];
                if (c > best) { best = c; bp = f; }   // first-max (jnp.argmax)
            }
            nfv[to] = best + ft[to];
            wrd |= (unsigned)bp << (4 * to);
        }
        #pragma unroll
        for (int i = 0; i < TAGS; i++) { fv[i] = nfv[i]; ft[i] = fn[i]; }
        if (tid == 0) bpw[t] = wrd;
    }

    float best = fv[0] + tr[4][0];   // STOP row
    int bt = 0;
    #pragma unroll
    for (int f = 1; f < TAGS; f++) {
        float c = fv[f] + tr[4][f];
        if (c > best) { best = c; bt = f; }
    }

    if (tid == 0) {
        int off = 0;
        if (out_size == 1) { out[0] = best; return; }
        if (out_size >= T + 1) { out[0] = best; off = 1; }
        int tag = bt;
        for (int t = T - 1; t >= 0; t--) {
            out[off + t] = (float)tag;
            tag = (int)((bpw[t] >> (4 * tag)) & 15u);
        }
    }
}

extern "C" void kernel_launch(void* const* d_in, const int* in_sizes, int n_in,
                              void* d_out, int out_size) {
    const int*   sent  = (const int*)  d_in[0];
    const float* emb   = (const float*)d_in[1];
    const float* wihf  = (const float*)d_in[2];
    const float* whhf  = (const float*)d_in[3];
    const float* bihf  = (const float*)d_in[4];
    const float* bhhf  = (const float*)d_in[5];
    const float* wihb  = (const float*)d_in[6];
    const float* whhb  = (const float*)d_in[7];
    const float* bihb  = (const float*)d_in[8];
    const float* bhhb  = (const float*)d_in[9];
    const float* Wout  = (const float*)d_in[10];
    const float* bout  = (const float*)d_in[11];
    const float* trans = (const float*)d_in[12];
    const float* h0    = (const float*)d_in[13];
    const float* c0    = (const float*)d_in[14];

    dim3 gz(2048 / 64, T / 64);
    k_zin<<<gz, 256>>>(sent, emb, wihf, wihb, bihf, bhhf, bihb, bhhb);

    // 16-CTA clusters (nonportable size): 2 clusters of 16, one per direction
    cudaFuncSetAttribute(k_lstm, cudaFuncAttributeNonPortableClusterSizeAllowed, 1);
    {
        cudaLaunchConfig_t cfg = {};
        cfg.gridDim = dim3(2 * CPD, 1, 1);
        cfg.blockDim = dim3(128, 1, 1);
        cfg.dynamicSmemBytes = 0;
        cfg.stream = 0;
        cudaLaunchAttribute at[1];
        at[0].id = cudaLaunchAttributeClusterDimension;
        at[0].val.clusterDim = {CPD, 1, 1};
        cfg.attrs = at;
        cfg.numAttrs = 1;
        cudaLaunchKernelEx(&cfg, k_lstm, whhf, whhb, h0, c0);
    }

    k_feats<<<T / 64, 384>>>(Wout, bout);

    int vsm_bytes = T * TAGS * 4 + T * 4;   // 114688
    cudaFuncSetAttribute(k_vit, cudaFuncAttributeMaxDynamicSharedMemorySize, vsm_bytes);
    k_vit<<<1, 256, vsm_bytes>>>(trans, (float*)d_out, out_size);
}